// round 1
// baseline (speedup 1.0000x reference)
#include <cuda_runtime.h>

// AnnularDilatedKNN: B=4, N=4096, C=64, SAMPLE=16, DILATED_RATE=2 -> NSAMPLE=32, K_out=16
// radius^2 = 256.
//
// Pipeline (3 graph-captured launches):
//   1) prep:   xyz [B,N,3] -> SoA x/y/z + precomputed |p|^2 (matches reference's
//              sq = (x*x + y*y) + z*z rounding, plain fp32 ops, no fma contraction)
//   2) query:  one warp per query point; ascending-index scan in chunks of 32 with
//              ballot-based ordered hit extraction; early exit at 31 hits.
//              d2 = (sq_n + sq_m) - 2*dot,  dot = fma-chain (gemm-style lowering).
//   3) gather: one thread per (b,n,k); writes are k-fastest -> fully coalesced;
//              feature rows read as float4 (L2-resident 4MB table).

#define NB   4
#define NP   4096
#define KOUT 16

__device__ float g_xs[NB * NP];
__device__ float g_ys[NB * NP];
__device__ float g_zs[NB * NP];
__device__ float g_sq[NB * NP];
__device__ int   g_ids[NB * NP * KOUT];

__global__ __launch_bounds__(256) void prep_kernel(const float* __restrict__ xyz) {
    const int i = blockIdx.x * 256 + threadIdx.x;
    if (i >= NB * NP) return;
    const float x = xyz[3 * i + 0];
    const float y = xyz[3 * i + 1];
    const float z = xyz[3 * i + 2];
    g_xs[i] = x;
    g_ys[i] = y;
    g_zs[i] = z;
    // jnp.sum(xyz*xyz, -1): left-to-right, separately rounded products (no fma).
    g_sq[i] = __fadd_rn(__fadd_rn(__fmul_rn(x, x), __fmul_rn(y, y)), __fmul_rn(z, z));
}

__global__ __launch_bounds__(256) void query_kernel() {
    __shared__ int sh_hits[8][32];
    const int warp = threadIdx.x >> 5;
    const int lane = threadIdx.x & 31;
    const int q = (blockIdx.x << 3) + warp;      // global query id, 0..16383
    const int b = q >> 12;
    const int n = q & (NP - 1);
    const int bb = b << 12;

    const float xn  = g_xs[bb + n];
    const float yn  = g_ys[bb + n];
    const float zn  = g_zs[bb + n];
    const float sqn = g_sq[bb + n];

    if (lane == 0) sh_hits[warp][0] = 0;  // paranoia init (self is always in ball)
    int cnt = 0;

    for (int base = 0; base < NP; base += 32) {
        const int m = base + lane;
        const float xm  = g_xs[bb + m];
        const float ym  = g_ys[bb + m];
        const float zm  = g_zs[bb + m];
        const float sqm = g_sq[bb + m];
        // einsum dot lowered gemm-style: fma chain over K=3
        const float dot = fmaf(zn, zm, fmaf(yn, ym, __fmul_rn(xn, xm)));
        // (sq_n + sq_m) - 2*dot, plain rounding
        const float d2 = __fsub_rn(__fadd_rn(sqn, sqm), __fmul_rn(2.0f, dot));
        const bool inball = d2 < 256.0f;
        const unsigned mask = __ballot_sync(0xffffffffu, inball);
        if (inball) {
            const int pos = cnt + __popc(mask & ((1u << lane) - 1u));
            if (pos < 31) sh_hits[warp][pos] = m;   // need only hits 0..30
        }
        cnt += __popc(mask);
        if (cnt >= 31) break;   // uniform across warp (cnt from ballot)
    }
    __syncwarp();

    if (lane < KOUT) {
        const int h0 = sh_hits[warp][0];            // center = first (smallest-index) hit
        int v = h0;
        if (lane > 0) {
            const int j = lane + 15;                // annular region: hits 16..30
            if (j < cnt) v = sh_hits[warp][j];      // else padded with center
        }
        g_ids[(q << 4) + lane] = v;
    }
}

__global__ __launch_bounds__(256) void gather_kernel(const float* __restrict__ xyz,
                                                     const float* __restrict__ feat,
                                                     float* __restrict__ out) {
    const int idx = blockIdx.x * 256 + threadIdx.x;   // 0..262143 = (b, n, k)
    const int id  = g_ids[idx];
    const int k   = idx & 15;
    const int n   = (idx >> 4) & (NP - 1);
    const int b   = idx >> 16;
    const int nk  = (n << 4) | k;                     // fastest in k -> coalesced writes

    // dilated_xyz: [B, 3, N, K]
    const float* src = xyz + ((b << 12) + id) * 3;
    float* oxyz = out + ((b * 3) << 16) + nk;
    oxyz[0]         = src[0];
    oxyz[1 << 16]   = src[1];
    oxyz[2 << 16]   = src[2];

    // dilated_feature: [B, 64, N, K] starting after the xyz block
    const float4* f4 = reinterpret_cast<const float4*>(feat) + (((b << 12) + id) << 4);
    float* ofeat = out + ((NB * 3) << 16) + ((b * 64) << 16) + nk;
    #pragma unroll
    for (int c4 = 0; c4 < 16; ++c4) {
        const float4 v = f4[c4];
        ofeat[((c4 * 4 + 0) << 16)] = v.x;
        ofeat[((c4 * 4 + 1) << 16)] = v.y;
        ofeat[((c4 * 4 + 2) << 16)] = v.z;
        ofeat[((c4 * 4 + 3) << 16)] = v.w;
    }
}

extern "C" void kernel_launch(void* const* d_in, const int* in_sizes, int n_in,
                              void* d_out, int out_size) {
    const float* xyz  = (const float*)d_in[0];
    const float* feat = (const float*)d_in[1];
    float* out = (float*)d_out;
    prep_kernel<<<(NB * NP + 255) / 256, 256>>>(xyz);
    query_kernel<<<(NB * NP) / 8, 256>>>();
    gather_kernel<<<(NB * NP * KOUT) / 256, 256>>>(xyz, feat, out);
}